// round 2
// baseline (speedup 1.0000x reference)
#include <cuda_runtime.h>
#include <cuda_bf16.h>
#include <math.h>

#define B_   16
#define NQ_  300
#define C_   256
#define H_   8
#define DH_  32
#define L_   3
#define P_   4
#define DFF_ 2048
#define LEN_IN_ 21504
#define MTGT (B_*NQ_)      // 4800
#define MV   (B_*LEN_IN_)  // 344064

// ---------------- scratch (device globals; no allocation allowed) ----------
__device__ float g_t2  [MTGT*C_];
__device__ float g_qk  [MTGT*C_];
__device__ float g_qkv [MTGT*3*C_];
__device__ float g_sa  [MTGT*C_];
__device__ float g_tgt1[MTGT*C_];
__device__ float g_tgt2[MTGT*C_];
__device__ float g_v   [(size_t)MV*C_];
__device__ float g_off [MTGT*H_*L_*P_*2];
__device__ float g_aw  [MTGT*H_*L_*P_];
__device__ float g_ca  [MTGT*C_];
__device__ float g_hid [MTGT*DFF_];

// ---------------- LayerNorm (+ optional pos add producing qk) ---------------
__global__ void __launch_bounds__(256) ln_kernel(
    const float* __restrict__ x, const float* __restrict__ g,
    const float* __restrict__ b, const float* __restrict__ pos,
    float* __restrict__ t2, float* __restrict__ qk)
{
    int row = blockIdx.x;
    int tid = threadIdx.x;
    size_t idx = (size_t)row * C_ + tid;
    float v = x[idx];

    __shared__ float red[8];
    float s = v;
    #pragma unroll
    for (int o = 16; o; o >>= 1) s += __shfl_xor_sync(0xffffffffu, s, o);
    if ((tid & 31) == 0) red[tid >> 5] = s;
    __syncthreads();
    float tot = 0.f;
    #pragma unroll
    for (int i = 0; i < 8; i++) tot += red[i];
    float mu = tot * (1.f / 256.f);
    float d = v - mu;
    __syncthreads();
    float s2 = d * d;
    #pragma unroll
    for (int o = 16; o; o >>= 1) s2 += __shfl_xor_sync(0xffffffffu, s2, o);
    if ((tid & 31) == 0) red[tid >> 5] = s2;
    __syncthreads();
    float tot2 = 0.f;
    #pragma unroll
    for (int i = 0; i < 8; i++) tot2 += red[i];
    float var = tot2 * (1.f / 256.f);

    float y = d * rsqrtf(var + 1e-5f) * g[tid] + b[tid];
    t2[idx] = y;
    if (pos) qk[idx] = y + pos[idx];
}

// ---------------- Generic GEMM: C[M,N] = A[M,K] @ W[N,K]^T + bias ----------
// epi: 0=bias  1=bias+relu  2=bias+residual  3=bias+mask-zero(per row)
__global__ void __launch_bounds__(256) gemm_abt(
    const float* __restrict__ A, const float* __restrict__ W,
    const float* __restrict__ bias, const float* __restrict__ resid,
    const unsigned char* __restrict__ mask,
    float* __restrict__ Cc, int M, int N, int K, int ldc, int coloff, int epi)
{
    __shared__ __align__(16) float As[16][68];
    __shared__ __align__(16) float Ws[16][68];

    int tid  = threadIdx.x;
    int row0 = blockIdx.y * 64;
    int col0 = blockIdx.x * 64;
    int ty = tid >> 4, tx = tid & 15;
    int lrow = tid >> 2, lk = (tid & 3) * 4;

    float acc[4][4];
    #pragma unroll
    for (int i = 0; i < 4; i++)
        #pragma unroll
        for (int j = 0; j < 4; j++) acc[i][j] = 0.f;

    bool avalid = (row0 + lrow) < M;
    bool wvalid = (col0 + lrow) < N;
    const float* Ap = A + (size_t)(row0 + lrow) * K + lk;
    const float* Wp = W + (size_t)(col0 + lrow) * K + lk;

    for (int k0 = 0; k0 < K; k0 += 16) {
        float4 av = avalid ? *(const float4*)(Ap + k0) : make_float4(0.f,0.f,0.f,0.f);
        float4 wv = wvalid ? *(const float4*)(Wp + k0) : make_float4(0.f,0.f,0.f,0.f);
        As[lk+0][lrow] = av.x; As[lk+1][lrow] = av.y;
        As[lk+2][lrow] = av.z; As[lk+3][lrow] = av.w;
        Ws[lk+0][lrow] = wv.x; Ws[lk+1][lrow] = wv.y;
        Ws[lk+2][lrow] = wv.z; Ws[lk+3][lrow] = wv.w;
        __syncthreads();
        #pragma unroll
        for (int kk = 0; kk < 16; kk++) {
            float4 a4 = *(const float4*)&As[kk][ty * 4];
            float4 w4 = *(const float4*)&Ws[kk][tx * 4];
            acc[0][0] += a4.x*w4.x; acc[0][1] += a4.x*w4.y; acc[0][2] += a4.x*w4.z; acc[0][3] += a4.x*w4.w;
            acc[1][0] += a4.y*w4.x; acc[1][1] += a4.y*w4.y; acc[1][2] += a4.y*w4.z; acc[1][3] += a4.y*w4.w;
            acc[2][0] += a4.z*w4.x; acc[2][1] += a4.z*w4.y; acc[2][2] += a4.z*w4.z; acc[2][3] += a4.z*w4.w;
            acc[3][0] += a4.w*w4.x; acc[3][1] += a4.w*w4.y; acc[3][2] += a4.w*w4.z; acc[3][3] += a4.w*w4.w;
        }
        __syncthreads();
    }

    #pragma unroll
    for (int i = 0; i < 4; i++) {
        int r = row0 + ty * 4 + i;
        if (r >= M) continue;
        bool mz = (epi == 3) && mask[r];
        #pragma unroll
        for (int j = 0; j < 4; j++) {
            int c = col0 + tx * 4 + j;
            if (c >= N) continue;
            float vv = acc[i][j] + bias[c];
            if (epi == 1) vv = fmaxf(vv, 0.f);
            else if (epi == 2) vv += resid[(size_t)r * ldc + coloff + c];
            else if (epi == 3 && mz) vv = 0.f;
            Cc[(size_t)r * ldc + coloff + c] = vv;
        }
    }
}

// ---------------- Self-attention (flash-style, one block per (b,h)) --------
__global__ void __launch_bounds__(256) attn_kernel(
    const float* __restrict__ qkv, float* __restrict__ sa)
{
    int b = blockIdx.x / H_;
    int h = blockIdx.x % H_;
    extern __shared__ float sm[];
    float* Ks = sm;
    float* Vs = sm + NQ_ * DH_;
    int tid = threadIdx.x;

    for (int i = tid; i < NQ_ * DH_; i += 256) {
        int r = i >> 5, d = i & 31;
        const float* base = qkv + ((size_t)(b * NQ_ + r)) * 768 + h * 32 + d;
        Ks[i] = base[256];
        Vs[i] = base[512];
    }
    __syncthreads();

    for (int q = tid; q < NQ_; q += 256) {
        float4 qv[8];
        const float4* qb = (const float4*)(qkv + ((size_t)(b * NQ_ + q)) * 768 + h * 32);
        #pragma unroll
        for (int u = 0; u < 8; u++) qv[u] = qb[u];

        float m = -1e30f, s = 0.f;
        float acc[32];
        #pragma unroll
        for (int d = 0; d < 32; d++) acc[d] = 0.f;

        for (int k = 0; k < NQ_; k++) {
            const float4* kb = (const float4*)(Ks + k * 32);
            float dot = 0.f;
            #pragma unroll
            for (int u = 0; u < 8; u++) {
                float4 kv = kb[u];
                dot += qv[u].x * kv.x + qv[u].y * kv.y + qv[u].z * kv.z + qv[u].w * kv.w;
            }
            dot *= 0.17677669529663687f;   // 1/sqrt(32)
            float nm = fmaxf(m, dot);
            float corr = __expf(m - nm);
            float e = __expf(dot - nm);
            s = s * corr + e;
            const float4* vb = (const float4*)(Vs + k * 32);
            #pragma unroll
            for (int u = 0; u < 8; u++) {
                float4 vv = vb[u];
                acc[4*u+0] = acc[4*u+0] * corr + e * vv.x;
                acc[4*u+1] = acc[4*u+1] * corr + e * vv.y;
                acc[4*u+2] = acc[4*u+2] * corr + e * vv.z;
                acc[4*u+3] = acc[4*u+3] * corr + e * vv.w;
            }
            m = nm;
        }
        float inv = 1.f / s;
        float* outp = sa + ((size_t)(b * NQ_ + q)) * C_ + h * 32;
        #pragma unroll
        for (int d = 0; d < 32; d++) outp[d] = acc[d] * inv;
    }
}

// ---------------- Deformable sampling (warp per head, lane = channel) -------
__global__ void __launch_bounds__(256) deform_kernel(
    const float* __restrict__ v, const float* __restrict__ offb,
    const float* __restrict__ awb, const float* __restrict__ refp,
    float* __restrict__ ca)
{
    int bq = blockIdx.x;               // b*NQ + q
    int h = threadIdx.x >> 5;
    int lane = threadIdx.x & 31;

    // softmax over L*P = 12 attention weights, fused via shuffles
    float lg = (lane < 12) ? awb[(size_t)bq * 96 + h * 12 + lane] : -INFINITY;
    float mx = lg;
    #pragma unroll
    for (int o = 16; o; o >>= 1) mx = fmaxf(mx, __shfl_xor_sync(0xffffffffu, mx, o));
    float e = (lane < 12) ? __expf(lg - mx) : 0.f;
    float ssum = e;
    #pragma unroll
    for (int o = 16; o; o >>= 1) ssum += __shfl_xor_sync(0xffffffffu, ssum, o);
    float myaw = e / ssum;

    const int Wl[3] = {128, 64, 32};
    const int Hl[3] = {128, 64, 32};
    const int st[3] = {0, 16384, 20480};

    float acc = 0.f;
    const float* offrow = offb + (size_t)bq * 192 + h * 24;
    const float* refrow = refp + (size_t)bq * 6;
    int bbase = (bq / NQ_) * LEN_IN_;

    #pragma unroll
    for (int l = 0; l < 3; l++) {
        float Wf = (float)Wl[l], Hf = (float)Hl[l];
        float rx = refrow[l * 2 + 0];
        float ry = refrow[l * 2 + 1];
        #pragma unroll
        for (int p = 0; p < 4; p++) {
            float ox = offrow[(l * 4 + p) * 2 + 0];
            float oy = offrow[(l * 4 + p) * 2 + 1];
            float lx = rx + ox / Wf;
            float ly = ry + oy / Hf;
            float x = lx * Wf - 0.5f;
            float y = ly * Hf - 0.5f;
            float x0 = floorf(x), y0 = floorf(y);
            float fx = x - x0, fy = y - y0;
            int ix = (int)x0, iy = (int)y0;
            float a = __shfl_sync(0xffffffffu, myaw, l * 4 + p);
            #pragma unroll
            for (int dy = 0; dy < 2; dy++) {
                int yi = iy + dy;
                if (yi < 0 || yi >= Hl[l]) continue;
                float wy = dy ? fy : (1.f - fy);
                #pragma unroll
                for (int dx = 0; dx < 2; dx++) {
                    int xi = ix + dx;
                    if (xi < 0 || xi >= Wl[l]) continue;
                    float w = wy * (dx ? fx : (1.f - fx));
                    int pos = st[l] + yi * Wl[l] + xi;
                    acc += a * w * v[((size_t)(bbase + pos) * H_ + h) * DH_ + lane];
                }
            }
        }
    }
    ca[(size_t)bq * C_ + h * DH_ + lane] = acc;
}

// ---------------------------------------------------------------------------
extern "C" void kernel_launch(void* const* d_in, const int* in_sizes, int n_in,
                              void* d_out, int out_size)
{
    const float* tgt        = (const float*)d_in[0];
    const float* memory     = (const float*)d_in[1];
    const float* query_pos  = (const float*)d_in[3];
    const float* qref       = (const float*)d_in[5];
    const unsigned char* kpm = (const unsigned char*)d_in[7];
    const float* ln1g = (const float*)d_in[9];
    const float* ln1b = (const float*)d_in[10];
    const float* ln2g = (const float*)d_in[11];
    const float* ln2b = (const float*)d_in[12];
    const float* ln3g = (const float*)d_in[13];
    const float* ln3b = (const float*)d_in[14];
    const float* attn_in_w  = (const float*)d_in[15];
    const float* attn_in_b  = (const float*)d_in[16];
    const float* attn_out_w = (const float*)d_in[17];
    const float* attn_out_b = (const float*)d_in[18];
    const float* off_w  = (const float*)d_in[19];
    const float* off_b  = (const float*)d_in[20];
    const float* aw_w   = (const float*)d_in[21];
    const float* aw_b   = (const float*)d_in[22];
    const float* vproj_w = (const float*)d_in[23];
    const float* vproj_b = (const float*)d_in[24];
    const float* oproj_w = (const float*)d_in[25];
    const float* oproj_b = (const float*)d_in[26];
    const float* ffn1_w = (const float*)d_in[27];
    const float* ffn1_b = (const float*)d_in[28];
    const float* ffn2_w = (const float*)d_in[29];
    const float* ffn2_b = (const float*)d_in[30];
    float* out = (float*)d_out;

    float *p_t2, *p_qk, *p_qkv, *p_sa, *p_tgt1, *p_tgt2, *p_v, *p_off, *p_aw, *p_ca, *p_hid;
    cudaGetSymbolAddress((void**)&p_t2,   g_t2);
    cudaGetSymbolAddress((void**)&p_qk,   g_qk);
    cudaGetSymbolAddress((void**)&p_qkv,  g_qkv);
    cudaGetSymbolAddress((void**)&p_sa,   g_sa);
    cudaGetSymbolAddress((void**)&p_tgt1, g_tgt1);
    cudaGetSymbolAddress((void**)&p_tgt2, g_tgt2);
    cudaGetSymbolAddress((void**)&p_v,    g_v);
    cudaGetSymbolAddress((void**)&p_off,  g_off);
    cudaGetSymbolAddress((void**)&p_aw,   g_aw);
    cudaGetSymbolAddress((void**)&p_ca,   g_ca);
    cudaGetSymbolAddress((void**)&p_hid,  g_hid);

    int attn_smem = NQ_ * DH_ * 2 * sizeof(float);   // 76800
    cudaFuncSetAttribute(attn_kernel, cudaFuncAttributeMaxDynamicSharedMemorySize, attn_smem);

    dim3 blk(256);

    // 1) LN1 -> t2, qk = t2 + query_pos
    ln_kernel<<<MTGT, blk>>>(tgt, ln1g, ln1b, query_pos, p_t2, p_qk);

    // 2) Q,K = qk @ Wqk^T (cols 0..511 of qkv);  V = t2 @ Wv^T (cols 512..767)
    gemm_abt<<<dim3(512/64, MTGT/64), blk>>>(p_qk, attn_in_w, attn_in_b,
        nullptr, nullptr, p_qkv, MTGT, 512, C_, 768, 0, 0);
    gemm_abt<<<dim3(256/64, MTGT/64), blk>>>(p_t2, attn_in_w + 512*C_, attn_in_b + 512,
        nullptr, nullptr, p_qkv, MTGT, 256, C_, 768, 512, 0);

    // 3) self-attention -> sa [B,NQ,C]
    attn_kernel<<<B_ * H_, blk, attn_smem>>>(p_qkv, p_sa);

    // 4) tgt1 = tgt + sa @ attn_out_w^T + b
    gemm_abt<<<dim3(4, MTGT/64), blk>>>(p_sa, attn_out_w, attn_out_b,
        tgt, nullptr, p_tgt1, MTGT, C_, C_, C_, 0, 2);

    // 5) LN2 -> t2
    ln_kernel<<<MTGT, blk>>>(p_tgt1, ln2g, ln2b, nullptr, p_t2, nullptr);

    // 6) v = memory @ vproj^T + b, masked  (dominant GEMM)
    gemm_abt<<<dim3(4, MV/64), blk>>>(memory, vproj_w, vproj_b,
        nullptr, kpm, p_v, MV, C_, C_, C_, 0, 3);

    // 7) offsets and attention-weight logits
    gemm_abt<<<dim3(3, MTGT/64), blk>>>(p_t2, off_w, off_b,
        nullptr, nullptr, p_off, MTGT, 192, C_, 192, 0, 0);
    gemm_abt<<<dim3(2, MTGT/64), blk>>>(p_t2, aw_w, aw_b,
        nullptr, nullptr, p_aw, MTGT, 96, C_, 96, 0, 0);

    // 8) deformable sampling (softmax fused) -> ca
    deform_kernel<<<MTGT, blk>>>(p_v, p_off, p_aw, qref, p_ca);

    // 9) tgt2 = tgt1 + ca @ oproj^T + b
    gemm_abt<<<dim3(4, MTGT/64), blk>>>(p_ca, oproj_w, oproj_b,
        p_tgt1, nullptr, p_tgt2, MTGT, C_, C_, C_, 0, 2);

    // 10) LN3 -> t2
    ln_kernel<<<MTGT, blk>>>(p_tgt2, ln3g, ln3b, nullptr, p_t2, nullptr);

    // 11) FFN
    gemm_abt<<<dim3(DFF_/64, MTGT/64), blk>>>(p_t2, ffn1_w, ffn1_b,
        nullptr, nullptr, p_hid, MTGT, DFF_, C_, DFF_, 0, 1);
    gemm_abt<<<dim3(4, MTGT/64), blk>>>(p_hid, ffn2_w, ffn2_b,
        p_tgt2, nullptr, out, MTGT, C_, DFF_, C_, 0, 2);
}

// round 3
// speedup vs baseline: 1.6028x; 1.6028x over previous
#include <cuda_runtime.h>
#include <cuda_bf16.h>
#include <math.h>

#define B_   16
#define NQ_  300
#define C_   256
#define H_   8
#define DH_  32
#define L_   3
#define P_   4
#define DFF_ 2048
#define LEN_IN_ 21504
#define MTGT (B_*NQ_)      // 4800
#define MV   (B_*LEN_IN_)  // 344064

// ---------------- scratch (device globals; no allocation allowed) ----------
__device__ float g_t2  [MTGT*C_];
__device__ float g_qk  [MTGT*C_];
__device__ float g_qkv [MTGT*3*C_];
__device__ float g_sa  [MTGT*C_];
__device__ float g_tgt1[MTGT*C_];
__device__ float g_tgt2[MTGT*C_];
__device__ float g_v   [(size_t)MV*C_];
__device__ float g_off [MTGT*H_*L_*P_*2];
__device__ float g_aw  [MTGT*H_*L_*P_];
__device__ float g_ca  [MTGT*C_];
__device__ float g_hid [MTGT*DFF_];

// ---------------- LayerNorm (+ optional pos add producing qk) ---------------
__global__ void __launch_bounds__(256) ln_kernel(
    const float* __restrict__ x, const float* __restrict__ g,
    const float* __restrict__ b, const float* __restrict__ pos,
    float* __restrict__ t2, float* __restrict__ qk)
{
    int row = blockIdx.x;
    int tid = threadIdx.x;
    size_t idx = (size_t)row * C_ + tid;
    float v = x[idx];

    __shared__ float red[8];
    float s = v;
    #pragma unroll
    for (int o = 16; o; o >>= 1) s += __shfl_xor_sync(0xffffffffu, s, o);
    if ((tid & 31) == 0) red[tid >> 5] = s;
    __syncthreads();
    float tot = 0.f;
    #pragma unroll
    for (int i = 0; i < 8; i++) tot += red[i];
    float mu = tot * (1.f / 256.f);
    float d = v - mu;
    __syncthreads();
    float s2 = d * d;
    #pragma unroll
    for (int o = 16; o; o >>= 1) s2 += __shfl_xor_sync(0xffffffffu, s2, o);
    if ((tid & 31) == 0) red[tid >> 5] = s2;
    __syncthreads();
    float tot2 = 0.f;
    #pragma unroll
    for (int i = 0; i < 8; i++) tot2 += red[i];
    float var = tot2 * (1.f / 256.f);

    float y = d * rsqrtf(var + 1e-5f) * g[tid] + b[tid];
    t2[idx] = y;
    if (pos) qk[idx] = y + pos[idx];
}

// ======================= bf16x3 tensor-core GEMM ===========================
// C[M,N] = A[M,K] @ W[N,K]^T + bias, split-precision (hi/lo bf16, 3 MMAs).
// Tile: BM=128, BN=64, BK=16. 256 threads = 8 warps, warp tile 32x32.
// epi: 0=bias  1=bias+relu  2=bias+residual  3=bias+mask-zero(per row)

__device__ __forceinline__ void mma_bf16(
    float& c0, float& c1, float& c2, float& c3,
    unsigned a0, unsigned a1, unsigned a2, unsigned a3,
    unsigned b0, unsigned b1)
{
    asm volatile(
        "mma.sync.aligned.m16n8k16.row.col.f32.bf16.bf16.f32 "
        "{%0,%1,%2,%3}, {%4,%5,%6,%7}, {%8,%9}, {%0,%1,%2,%3};"
        : "+f"(c0), "+f"(c1), "+f"(c2), "+f"(c3)
        : "r"(a0), "r"(a1), "r"(a2), "r"(a3), "r"(b0), "r"(b1));
}

__device__ __forceinline__ void split2(float e0, float e1,
                                       unsigned& hi, unsigned& lo)
{
    __nv_bfloat16 h0 = __float2bfloat16_rn(e0);
    __nv_bfloat16 h1 = __float2bfloat16_rn(e1);
    float r0 = e0 - __bfloat162float(h0);
    float r1 = e1 - __bfloat162float(h1);
    __nv_bfloat162 hp; hp.x = h0; hp.y = h1;
    __nv_bfloat162 lp = __floats2bfloat162_rn(r0, r1);
    hi = *(unsigned*)&hp;
    lo = *(unsigned*)&lp;
}

__global__ void __launch_bounds__(256, 2) gemm_mma(
    const float* __restrict__ A, const float* __restrict__ W,
    const float* __restrict__ bias, const float* __restrict__ resid,
    const unsigned char* __restrict__ mask,
    float* __restrict__ Cc, int M, int N, int K, int ldc, int coloff, int epi)
{
    // Fragment-layout smem: A [8 mtiles][32 lanes][4 regs], B [4 pairs][32 lanes][2 sub][2 regs]
    __shared__ __align__(16) unsigned AsH[8*32*4];
    __shared__ __align__(16) unsigned AsL[8*32*4];
    __shared__ __align__(16) unsigned BsH[4*32*2*2];
    __shared__ __align__(16) unsigned BsL[4*32*2*2];

    int tid = threadIdx.x;
    int wid = tid >> 5, lane = tid & 31;
    int wm = wid & 3, wn = wid >> 2;
    int row0 = blockIdx.y * 128;
    int col0 = blockIdx.x * 64;

    // Staging assignments
    int arow = tid >> 1;                // 0..127
    int ak0  = (tid & 1) * 8;           // 0 or 8
    int brow = tid >> 2;                // 0..63 (n index)
    int bk0  = (tid & 3) * 4;           // 0,4,8,12

    int grow = row0 + arow;
    int gcol = col0 + brow;
    bool avalid = grow < M;
    bool bvalid = gcol < N;
    const float* Aptr = A + (size_t)grow * K + ak0;
    const float* Wptr = W + (size_t)gcol * K + bk0;

    // A staging destination indices (two float4s: k-base ak0 and ak0+4)
    int a_mt = arow >> 4;
    int a_g  = arow & 15;
    int a_laneg = a_g & 7;
    int a_regrow = a_g >> 3;

    // B staging destination indices
    int b_nt  = brow >> 3;
    int b_g   = brow & 7;
    int b_pair = b_nt >> 1;
    int b_sub  = b_nt & 1;

    float acc[2][4][4];
    #pragma unroll
    for (int i = 0; i < 2; i++)
        #pragma unroll
        for (int j = 0; j < 4; j++)
            #pragma unroll
            for (int r = 0; r < 4; r++) acc[i][j][r] = 0.f;

    float4 zf4 = make_float4(0.f, 0.f, 0.f, 0.f);
    float4 aR0 = avalid ? *(const float4*)(Aptr)     : zf4;
    float4 aR1 = avalid ? *(const float4*)(Aptr + 4) : zf4;
    float4 bR0 = bvalid ? *(const float4*)(Wptr)     : zf4;

    for (int kt = 0; kt < K; kt += 16) {
        // ---- store staged regs to smem fragment buffers (with hi/lo split)
        {
            // A float4 #1: k = ak0..ak0+3
            int reg = a_regrow + 2 * (ak0 >> 3);
            int t4  = (ak0 & 7) >> 1;
            unsigned hi, lo;
            int base = (a_mt * 32 + a_laneg * 4 + t4) * 4 + reg;
            split2(aR0.x, aR0.y, hi, lo); AsH[base] = hi; AsL[base] = lo;
            base = (a_mt * 32 + a_laneg * 4 + t4 + 1) * 4 + reg;
            split2(aR0.z, aR0.w, hi, lo); AsH[base] = hi; AsL[base] = lo;
            // A float4 #2: k = ak0+4..ak0+7
            int ak1 = ak0 + 4;
            reg = a_regrow + 2 * (ak1 >> 3);
            t4  = (ak1 & 7) >> 1;
            base = (a_mt * 32 + a_laneg * 4 + t4) * 4 + reg;
            split2(aR1.x, aR1.y, hi, lo); AsH[base] = hi; AsL[base] = lo;
            base = (a_mt * 32 + a_laneg * 4 + t4 + 1) * 4 + reg;
            split2(aR1.z, aR1.w, hi, lo); AsH[base] = hi; AsL[base] = lo;
            // B float4: k = bk0..bk0+3
            int breg = bk0 >> 3;
            int bt4  = (bk0 & 7) >> 1;
            base = ((b_pair * 32 + b_g * 4 + bt4) * 2 + b_sub) * 2 + breg;
            split2(bR0.x, bR0.y, hi, lo); BsH[base] = hi; BsL[base] = lo;
            base = ((b_pair * 32 + b_g * 4 + bt4 + 1) * 2 + b_sub) * 2 + breg;
            split2(bR0.z, bR0.w, hi, lo); BsH[base] = hi; BsL[base] = lo;
        }
        __syncthreads();

        // ---- prefetch next k-tile into registers (overlaps with MMA below)
        if (kt + 16 < K) {
            aR0 = avalid ? *(const float4*)(Aptr + kt + 16)     : zf4;
            aR1 = avalid ? *(const float4*)(Aptr + kt + 16 + 4) : zf4;
            bR0 = bvalid ? *(const float4*)(Wptr + kt + 16)     : zf4;
        }

        // ---- consume fragments
        uint4 aH[2], aL[2], bH[2], bL[2];
        #pragma unroll
        for (int mt = 0; mt < 2; mt++) {
            int idx = ((wm * 2 + mt) * 32 + lane) * 4;
            aH[mt] = *(const uint4*)&AsH[idx];
            aL[mt] = *(const uint4*)&AsL[idx];
        }
        #pragma unroll
        for (int np = 0; np < 2; np++) {
            int idx = ((wn * 2 + np) * 32 + lane) * 4;
            bH[np] = *(const uint4*)&BsH[idx];
            bL[np] = *(const uint4*)&BsL[idx];
        }
        #pragma unroll
        for (int mt = 0; mt < 2; mt++) {
            #pragma unroll
            for (int nt = 0; nt < 4; nt++) {
                int np = nt >> 1, sub = nt & 1;
                unsigned bh0 = sub ? bH[np].z : bH[np].x;
                unsigned bh1 = sub ? bH[np].w : bH[np].y;
                unsigned bl0 = sub ? bL[np].z : bL[np].x;
                unsigned bl1 = sub ? bL[np].w : bL[np].y;
                float* c = acc[mt][nt];
                mma_bf16(c[0], c[1], c[2], c[3],
                         aH[mt].x, aH[mt].y, aH[mt].z, aH[mt].w, bh0, bh1);
                mma_bf16(c[0], c[1], c[2], c[3],
                         aH[mt].x, aH[mt].y, aH[mt].z, aH[mt].w, bl0, bl1);
                mma_bf16(c[0], c[1], c[2], c[3],
                         aL[mt].x, aL[mt].y, aL[mt].z, aL[mt].w, bh0, bh1);
            }
        }
        __syncthreads();
    }

    // ---- epilogue
    int g = lane >> 2, t4 = lane & 3;
    #pragma unroll
    for (int mt = 0; mt < 2; mt++) {
        #pragma unroll
        for (int nt = 0; nt < 4; nt++) {
            int r = row0 + wm * 32 + mt * 16 + g;
            int c = col0 + wn * 32 + nt * 8 + t4 * 2;
            if (c >= N) continue;
            float b0 = bias[c], b1 = bias[c + 1];
            #pragma unroll
            for (int half = 0; half < 2; half++) {
                int rr = r + half * 8;
                if (rr >= M) continue;
                float v0 = acc[mt][nt][half * 2 + 0] + b0;
                float v1 = acc[mt][nt][half * 2 + 1] + b1;
                if (epi == 1) { v0 = fmaxf(v0, 0.f); v1 = fmaxf(v1, 0.f); }
                else if (epi == 2) {
                    const float* rp = resid + (size_t)rr * ldc + coloff + c;
                    v0 += rp[0]; v1 += rp[1];
                }
                else if (epi == 3 && mask[rr]) { v0 = 0.f; v1 = 0.f; }
                float2 o; o.x = v0; o.y = v1;
                *(float2*)(Cc + (size_t)rr * ldc + coloff + c) = o;
            }
        }
    }
}

// ---------------- Self-attention (flash-style, one block per (b,h)) --------
__global__ void __launch_bounds__(256) attn_kernel(
    const float* __restrict__ qkv, float* __restrict__ sa)
{
    int b = blockIdx.x / H_;
    int h = blockIdx.x % H_;
    extern __shared__ float sm[];
    float* Ks = sm;
    float* Vs = sm + NQ_ * DH_;
    int tid = threadIdx.x;

    for (int i = tid; i < NQ_ * DH_; i += 256) {
        int r = i >> 5, d = i & 31;
        const float* base = qkv + ((size_t)(b * NQ_ + r)) * 768 + h * 32 + d;
        Ks[i] = base[256];
        Vs[i] = base[512];
    }
    __syncthreads();

    for (int q = tid; q < NQ_; q += 256) {
        float4 qv[8];
        const float4* qb = (const float4*)(qkv + ((size_t)(b * NQ_ + q)) * 768 + h * 32);
        #pragma unroll
        for (int u = 0; u < 8; u++) qv[u] = qb[u];

        float m = -1e30f, s = 0.f;
        float acc[32];
        #pragma unroll
        for (int d = 0; d < 32; d++) acc[d] = 0.f;

        for (int k = 0; k < NQ_; k++) {
            const float4* kb = (const float4*)(Ks + k * 32);
            float dot = 0.f;
            #pragma unroll
            for (int u = 0; u < 8; u++) {
                float4 kv = kb[u];
                dot += qv[u].x * kv.x + qv[u].y * kv.y + qv[u].z * kv.z + qv[u].w * kv.w;
            }
            dot *= 0.17677669529663687f;   // 1/sqrt(32)
            float nm = fmaxf(m, dot);
            float corr = __expf(m - nm);
            float e = __expf(dot - nm);
            s = s * corr + e;
            const float4* vb = (const float4*)(Vs + k * 32);
            #pragma unroll
            for (int u = 0; u < 8; u++) {
                float4 vv = vb[u];
                acc[4*u+0] = acc[4*u+0] * corr + e * vv.x;
                acc[4*u+1] = acc[4*u+1] * corr + e * vv.y;
                acc[4*u+2] = acc[4*u+2] * corr + e * vv.z;
                acc[4*u+3] = acc[4*u+3] * corr + e * vv.w;
            }
            m = nm;
        }
        float inv = 1.f / s;
        float* outp = sa + ((size_t)(b * NQ_ + q)) * C_ + h * 32;
        #pragma unroll
        for (int d = 0; d < 32; d++) outp[d] = acc[d] * inv;
    }
}

// ---------------- Deformable sampling (warp per head, lane = channel) -------
__global__ void __launch_bounds__(256) deform_kernel(
    const float* __restrict__ v, const float* __restrict__ offb,
    const float* __restrict__ awb, const float* __restrict__ refp,
    float* __restrict__ ca)
{
    int bq = blockIdx.x;               // b*NQ + q
    int h = threadIdx.x >> 5;
    int lane = threadIdx.x & 31;

    float lg = (lane < 12) ? awb[(size_t)bq * 96 + h * 12 + lane] : -INFINITY;
    float mx = lg;
    #pragma unroll
    for (int o = 16; o; o >>= 1) mx = fmaxf(mx, __shfl_xor_sync(0xffffffffu, mx, o));
    float e = (lane < 12) ? __expf(lg - mx) : 0.f;
    float ssum = e;
    #pragma unroll
    for (int o = 16; o; o >>= 1) ssum += __shfl_xor_sync(0xffffffffu, ssum, o);
    float myaw = e / ssum;

    const int Wl[3] = {128, 64, 32};
    const int Hl[3] = {128, 64, 32};
    const int st[3] = {0, 16384, 20480};

    float acc = 0.f;
    const float* offrow = offb + (size_t)bq * 192 + h * 24;
    const float* refrow = refp + (size_t)bq * 6;
    int bbase = (bq / NQ_) * LEN_IN_;

    #pragma unroll
    for (int l = 0; l < 3; l++) {
        float Wf = (float)Wl[l], Hf = (float)Hl[l];
        float rx = refrow[l * 2 + 0];
        float ry = refrow[l * 2 + 1];
        #pragma unroll
        for (int p = 0; p < 4; p++) {
            float ox = offrow[(l * 4 + p) * 2 + 0];
            float oy = offrow[(l * 4 + p) * 2 + 1];
            float lx = rx + ox / Wf;
            float ly = ry + oy / Hf;
            float x = lx * Wf - 0.5f;
            float y = ly * Hf - 0.5f;
            float x0 = floorf(x), y0 = floorf(y);
            float fx = x - x0, fy = y - y0;
            int ix = (int)x0, iy = (int)y0;
            float a = __shfl_sync(0xffffffffu, myaw, l * 4 + p);
            #pragma unroll
            for (int dy = 0; dy < 2; dy++) {
                int yi = iy + dy;
                if (yi < 0 || yi >= Hl[l]) continue;
                float wy = dy ? fy : (1.f - fy);
                #pragma unroll
                for (int dx = 0; dx < 2; dx++) {
                    int xi = ix + dx;
                    if (xi < 0 || xi >= Wl[l]) continue;
                    float w = wy * (dx ? fx : (1.f - fx));
                    int pos = st[l] + yi * Wl[l] + xi;
                    acc += a * w * v[((size_t)(bbase + pos) * H_ + h) * DH_ + lane];
                }
            }
        }
    }
    ca[(size_t)bq * C_ + h * DH_ + lane] = acc;
}

// ---------------------------------------------------------------------------
extern "C" void kernel_launch(void* const* d_in, const int* in_sizes, int n_in,
                              void* d_out, int out_size)
{
    const float* tgt        = (const float*)d_in[0];
    const float* memory     = (const float*)d_in[1];
    const float* query_pos  = (const float*)d_in[3];
    const float* qref       = (const float*)d_in[5];
    const unsigned char* kpm = (const unsigned char*)d_in[7];
    const float* ln1g = (const float*)d_in[9];
    const float* ln1b = (const float*)d_in[10];
    const float* ln2g = (const float*)d_in[11];
    const float* ln2b = (const float*)d_in[12];
    const float* ln3g = (const float*)d_in[13];
    const float* ln3b = (const float*)d_in[14];
    const float* attn_in_w  = (const float*)d_in[15];
    const float* attn_in_b  = (const float*)d_in[16];
    const float* attn_out_w = (const float*)d_in[17];
    const float* attn_out_b = (const float*)d_in[18];
    const float* off_w  = (const float*)d_in[19];
    const float* off_b  = (const float*)d_in[20];
    const float* aw_w   = (const float*)d_in[21];
    const float* aw_b   = (const float*)d_in[22];
    const float* vproj_w = (const float*)d_in[23];
    const float* vproj_b = (const float*)d_in[24];
    const float* oproj_w = (const float*)d_in[25];
    const float* oproj_b = (const float*)d_in[26];
    const float* ffn1_w = (const float*)d_in[27];
    const float* ffn1_b = (const float*)d_in[28];
    const float* ffn2_w = (const float*)d_in[29];
    const float* ffn2_b = (const float*)d_in[30];
    float* out = (float*)d_out;

    float *p_t2, *p_qk, *p_qkv, *p_sa, *p_tgt1, *p_tgt2, *p_v, *p_off, *p_aw, *p_ca, *p_hid;
    cudaGetSymbolAddress((void**)&p_t2,   g_t2);
    cudaGetSymbolAddress((void**)&p_qk,   g_qk);
    cudaGetSymbolAddress((void**)&p_qkv,  g_qkv);
    cudaGetSymbolAddress((void**)&p_sa,   g_sa);
    cudaGetSymbolAddress((void**)&p_tgt1, g_tgt1);
    cudaGetSymbolAddress((void**)&p_tgt2, g_tgt2);
    cudaGetSymbolAddress((void**)&p_v,    g_v);
    cudaGetSymbolAddress((void**)&p_off,  g_off);
    cudaGetSymbolAddress((void**)&p_aw,   g_aw);
    cudaGetSymbolAddress((void**)&p_ca,   g_ca);
    cudaGetSymbolAddress((void**)&p_hid,  g_hid);

    int attn_smem = NQ_ * DH_ * 2 * sizeof(float);   // 76800
    cudaFuncSetAttribute(attn_kernel, cudaFuncAttributeMaxDynamicSharedMemorySize, attn_smem);

    dim3 blk(256);
    const int MT_TILES = (MTGT + 127) / 128;   // 38
    const int MV_TILES = MV / 128;             // 2688

    // 1) LN1 -> t2, qk = t2 + query_pos
    ln_kernel<<<MTGT, blk>>>(tgt, ln1g, ln1b, query_pos, p_t2, p_qk);

    // 2) Q,K = qk @ Wqk^T ; V = t2 @ Wv^T  (into qkv[.,768])
    gemm_mma<<<dim3(8, MT_TILES), blk>>>(p_qk, attn_in_w, attn_in_b,
        nullptr, nullptr, p_qkv, MTGT, 512, C_, 768, 0, 0);
    gemm_mma<<<dim3(4, MT_TILES), blk>>>(p_t2, attn_in_w + 512*C_, attn_in_b + 512,
        nullptr, nullptr, p_qkv, MTGT, 256, C_, 768, 512, 0);

    // 3) self-attention -> sa
    attn_kernel<<<B_ * H_, blk, attn_smem>>>(p_qkv, p_sa);

    // 4) tgt1 = tgt + sa @ attn_out_w^T + b
    gemm_mma<<<dim3(4, MT_TILES), blk>>>(p_sa, attn_out_w, attn_out_b,
        tgt, nullptr, p_tgt1, MTGT, C_, C_, C_, 0, 2);

    // 5) LN2 -> t2
    ln_kernel<<<MTGT, blk>>>(p_tgt1, ln2g, ln2b, nullptr, p_t2, nullptr);

    // 6) v = memory @ vproj^T + b, masked  (dominant GEMM)
    gemm_mma<<<dim3(4, MV_TILES), blk>>>(memory, vproj_w, vproj_b,
        nullptr, kpm, p_v, MV, C_, C_, C_, 0, 3);

    // 7) offsets and attention-weight logits
    gemm_mma<<<dim3(3, MT_TILES), blk>>>(p_t2, off_w, off_b,
        nullptr, nullptr, p_off, MTGT, 192, C_, 192, 0, 0);
    gemm_mma<<<dim3(2, MT_TILES), blk>>>(p_t2, aw_w, aw_b,
        nullptr, nullptr, p_aw, MTGT, 96, C_, 96, 0, 0);

    // 8) deformable sampling (softmax fused) -> ca
    deform_kernel<<<MTGT, blk>>>(p_v, p_off, p_aw, qref, p_ca);

    // 9) tgt2 = tgt1 + ca @ oproj^T + b
    gemm_mma<<<dim3(4, MT_TILES), blk>>>(p_ca, oproj_w, oproj_b,
        p_tgt1, nullptr, p_tgt2, MTGT, C_, C_, C_, 0, 2);

    // 10) LN3 -> t2
    ln_kernel<<<MTGT, blk>>>(p_tgt2, ln3g, ln3b, nullptr, p_t2, nullptr);

    // 11) FFN
    gemm_mma<<<dim3(DFF_/64, MT_TILES), blk>>>(p_t2, ffn1_w, ffn1_b,
        nullptr, nullptr, p_hid, MTGT, DFF_, C_, DFF_, 0, 1);
    gemm_mma<<<dim3(4, MT_TILES), blk>>>(p_hid, ffn2_w, ffn2_b,
        p_tgt2, nullptr, out, MTGT, C_, DFF_, C_, 0, 2);
}

// round 4
// speedup vs baseline: 1.9808x; 1.2359x over previous
#include <cuda_runtime.h>
#include <cuda_bf16.h>
#include <cuda_fp16.h>
#include <math.h>

#define B_   16
#define NQ_  300
#define C_   256
#define H_   8
#define DH_  32
#define L_   3
#define P_   4
#define DFF_ 2048
#define LEN_IN_ 21504
#define MTGT (B_*NQ_)      // 4800
#define MV   (B_*LEN_IN_)  // 344064

// ---------------- scratch (device globals; no allocation allowed) ----------
__device__ float g_t2  [MTGT*C_];
__device__ float g_qk  [MTGT*C_];
__device__ float g_qkv [MTGT*3*C_];
__device__ float g_sa  [MTGT*C_];
__device__ float g_tgt1[MTGT*C_];
__device__ float g_tgt2[MTGT*C_];
__device__ float g_v   [(size_t)MV*C_];
__device__ float g_off [MTGT*H_*L_*P_*2];
__device__ float g_aw  [MTGT*H_*L_*P_];
__device__ float g_ca  [MTGT*C_];
__device__ float g_hid [MTGT*DFF_];

// ---------------- LayerNorm (+ optional pos add producing qk) ---------------
__global__ void __launch_bounds__(256) ln_kernel(
    const float* __restrict__ x, const float* __restrict__ g,
    const float* __restrict__ b, const float* __restrict__ pos,
    float* __restrict__ t2, float* __restrict__ qk)
{
    int row = blockIdx.x;
    int tid = threadIdx.x;
    size_t idx = (size_t)row * C_ + tid;
    float v = x[idx];

    __shared__ float red[8];
    float s = v;
    #pragma unroll
    for (int o = 16; o; o >>= 1) s += __shfl_xor_sync(0xffffffffu, s, o);
    if ((tid & 31) == 0) red[tid >> 5] = s;
    __syncthreads();
    float tot = 0.f;
    #pragma unroll
    for (int i = 0; i < 8; i++) tot += red[i];
    float mu = tot * (1.f / 256.f);
    float d = v - mu;
    __syncthreads();
    float s2 = d * d;
    #pragma unroll
    for (int o = 16; o; o >>= 1) s2 += __shfl_xor_sync(0xffffffffu, s2, o);
    if ((tid & 31) == 0) red[tid >> 5] = s2;
    __syncthreads();
    float tot2 = 0.f;
    #pragma unroll
    for (int i = 0; i < 8; i++) tot2 += red[i];
    float var = tot2 * (1.f / 256.f);

    float y = d * rsqrtf(var + 1e-5f) * g[tid] + b[tid];
    t2[idx] = y;
    if (pos) qk[idx] = y + pos[idx];
}

// ======================= MMA helpers =======================================
__device__ __forceinline__ void mma_bf16(
    float& c0, float& c1, float& c2, float& c3,
    unsigned a0, unsigned a1, unsigned a2, unsigned a3,
    unsigned b0, unsigned b1)
{
    asm volatile(
        "mma.sync.aligned.m16n8k16.row.col.f32.bf16.bf16.f32 "
        "{%0,%1,%2,%3}, {%4,%5,%6,%7}, {%8,%9}, {%0,%1,%2,%3};"
        : "+f"(c0), "+f"(c1), "+f"(c2), "+f"(c3)
        : "r"(a0), "r"(a1), "r"(a2), "r"(a3), "r"(b0), "r"(b1));
}

__device__ __forceinline__ void mma_f16(
    float& c0, float& c1, float& c2, float& c3,
    unsigned a0, unsigned a1, unsigned a2, unsigned a3,
    unsigned b0, unsigned b1)
{
    asm volatile(
        "mma.sync.aligned.m16n8k16.row.col.f32.f16.f16.f32 "
        "{%0,%1,%2,%3}, {%4,%5,%6,%7}, {%8,%9}, {%0,%1,%2,%3};"
        : "+f"(c0), "+f"(c1), "+f"(c2), "+f"(c3)
        : "r"(a0), "r"(a1), "r"(a2), "r"(a3), "r"(b0), "r"(b1));
}

__device__ __forceinline__ void split2(float e0, float e1,
                                       unsigned& hi, unsigned& lo)
{
    __nv_bfloat16 h0 = __float2bfloat16_rn(e0);
    __nv_bfloat16 h1 = __float2bfloat16_rn(e1);
    float r0 = e0 - __bfloat162float(h0);
    float r1 = e1 - __bfloat162float(h1);
    __nv_bfloat162 hp; hp.x = h0; hp.y = h1;
    __nv_bfloat162 lp = __floats2bfloat162_rn(r0, r1);
    hi = *(unsigned*)&hp;
    lo = *(unsigned*)&lp;
}

__device__ __forceinline__ unsigned pack_h2(float e0, float e1)
{
    __half2 h = __floats2half2_rn(e0, e1);
    return *(unsigned*)&h;
}

// ======================= bf16x3 tensor-core GEMM ===========================
// C[M,N] = A[M,K] @ W[N,K]^T + bias. Tile 128x64x16, 8 warps, warp 32x32.
// epi: 0=bias  1=bias+relu  2=bias+residual  3=bias+mask-zero(per row)
__global__ void __launch_bounds__(256, 2) gemm_mma(
    const float* __restrict__ A, const float* __restrict__ W,
    const float* __restrict__ bias, const float* __restrict__ resid,
    const unsigned char* __restrict__ mask,
    float* __restrict__ Cc, int M, int N, int K, int ldc, int coloff, int epi)
{
    __shared__ __align__(16) unsigned AsH[8*32*4];
    __shared__ __align__(16) unsigned AsL[8*32*4];
    __shared__ __align__(16) unsigned BsH[4*32*2*2];
    __shared__ __align__(16) unsigned BsL[4*32*2*2];

    int tid = threadIdx.x;
    int wid = tid >> 5, lane = tid & 31;
    int wm = wid & 3, wn = wid >> 2;
    int row0 = blockIdx.y * 128;
    int col0 = blockIdx.x * 64;

    int arow = tid >> 1;
    int ak0  = (tid & 1) * 8;
    int brow = tid >> 2;
    int bk0  = (tid & 3) * 4;

    int grow = row0 + arow;
    int gcol = col0 + brow;
    bool avalid = grow < M;
    bool bvalid = gcol < N;
    const float* Aptr = A + (size_t)grow * K + ak0;
    const float* Wptr = W + (size_t)gcol * K + bk0;

    int a_mt = arow >> 4;
    int a_g  = arow & 15;
    int a_laneg = a_g & 7;
    int a_regrow = a_g >> 3;
    int b_nt  = brow >> 3;
    int b_g   = brow & 7;
    int b_pair = b_nt >> 1;
    int b_sub  = b_nt & 1;

    float acc[2][4][4];
    #pragma unroll
    for (int i = 0; i < 2; i++)
        #pragma unroll
        for (int j = 0; j < 4; j++)
            #pragma unroll
            for (int r = 0; r < 4; r++) acc[i][j][r] = 0.f;

    float4 zf4 = make_float4(0.f, 0.f, 0.f, 0.f);
    float4 aR0 = avalid ? *(const float4*)(Aptr)     : zf4;
    float4 aR1 = avalid ? *(const float4*)(Aptr + 4) : zf4;
    float4 bR0 = bvalid ? *(const float4*)(Wptr)     : zf4;

    for (int kt = 0; kt < K; kt += 16) {
        {
            int reg = a_regrow + 2 * (ak0 >> 3);
            int t4  = (ak0 & 7) >> 1;
            unsigned hi, lo;
            int base = (a_mt * 32 + a_laneg * 4 + t4) * 4 + reg;
            split2(aR0.x, aR0.y, hi, lo); AsH[base] = hi; AsL[base] = lo;
            base = (a_mt * 32 + a_laneg * 4 + t4 + 1) * 4 + reg;
            split2(aR0.z, aR0.w, hi, lo); AsH[base] = hi; AsL[base] = lo;
            int ak1 = ak0 + 4;
            reg = a_regrow + 2 * (ak1 >> 3);
            t4  = (ak1 & 7) >> 1;
            base = (a_mt * 32 + a_laneg * 4 + t4) * 4 + reg;
            split2(aR1.x, aR1.y, hi, lo); AsH[base] = hi; AsL[base] = lo;
            base = (a_mt * 32 + a_laneg * 4 + t4 + 1) * 4 + reg;
            split2(aR1.z, aR1.w, hi, lo); AsH[base] = hi; AsL[base] = lo;
            int breg = bk0 >> 3;
            int bt4  = (bk0 & 7) >> 1;
            base = ((b_pair * 32 + b_g * 4 + bt4) * 2 + b_sub) * 2 + breg;
            split2(bR0.x, bR0.y, hi, lo); BsH[base] = hi; BsL[base] = lo;
            base = ((b_pair * 32 + b_g * 4 + bt4 + 1) * 2 + b_sub) * 2 + breg;
            split2(bR0.z, bR0.w, hi, lo); BsH[base] = hi; BsL[base] = lo;
        }
        __syncthreads();

        if (kt + 16 < K) {
            aR0 = avalid ? *(const float4*)(Aptr + kt + 16)     : zf4;
            aR1 = avalid ? *(const float4*)(Aptr + kt + 16 + 4) : zf4;
            bR0 = bvalid ? *(const float4*)(Wptr + kt + 16)     : zf4;
        }

        uint4 aH[2], aL[2], bH[2], bL[2];
        #pragma unroll
        for (int mt = 0; mt < 2; mt++) {
            int idx = ((wm * 2 + mt) * 32 + lane) * 4;
            aH[mt] = *(const uint4*)&AsH[idx];
            aL[mt] = *(const uint4*)&AsL[idx];
        }
        #pragma unroll
        for (int np = 0; np < 2; np++) {
            int idx = ((wn * 2 + np) * 32 + lane) * 4;
            bH[np] = *(const uint4*)&BsH[idx];
            bL[np] = *(const uint4*)&BsL[idx];
        }
        #pragma unroll
        for (int mt = 0; mt < 2; mt++) {
            #pragma unroll
            for (int nt = 0; nt < 4; nt++) {
                int np = nt >> 1, sub = nt & 1;
                unsigned bh0 = sub ? bH[np].z : bH[np].x;
                unsigned bh1 = sub ? bH[np].w : bH[np].y;
                unsigned bl0 = sub ? bL[np].z : bL[np].x;
                unsigned bl1 = sub ? bL[np].w : bL[np].y;
                float* c = acc[mt][nt];
                mma_bf16(c[0], c[1], c[2], c[3],
                         aH[mt].x, aH[mt].y, aH[mt].z, aH[mt].w, bh0, bh1);
                mma_bf16(c[0], c[1], c[2], c[3],
                         aH[mt].x, aH[mt].y, aH[mt].z, aH[mt].w, bl0, bl1);
                mma_bf16(c[0], c[1], c[2], c[3],
                         aL[mt].x, aL[mt].y, aL[mt].z, aL[mt].w, bh0, bh1);
            }
        }
        __syncthreads();
    }

    int g = lane >> 2, t4 = lane & 3;
    #pragma unroll
    for (int mt = 0; mt < 2; mt++) {
        #pragma unroll
        for (int nt = 0; nt < 4; nt++) {
            int r = row0 + wm * 32 + mt * 16 + g;
            int c = col0 + wn * 32 + nt * 8 + t4 * 2;
            if (c >= N) continue;
            float b0 = bias[c], b1 = bias[c + 1];
            #pragma unroll
            for (int half = 0; half < 2; half++) {
                int rr = r + half * 8;
                if (rr >= M) continue;
                float v0 = acc[mt][nt][half * 2 + 0] + b0;
                float v1 = acc[mt][nt][half * 2 + 1] + b1;
                if (epi == 1) { v0 = fmaxf(v0, 0.f); v1 = fmaxf(v1, 0.f); }
                else if (epi == 2) {
                    const float* rp = resid + (size_t)rr * ldc + coloff + c;
                    v0 += rp[0]; v1 += rp[1];
                }
                else if (epi == 3 && mask[rr]) { v0 = 0.f; v1 = 0.f; }
                float2 o; o.x = v0; o.y = v1;
                *(float2*)(Cc + (size_t)rr * ldc + coloff + c) = o;
            }
        }
    }
}

// ======================= fp16x1 tensor-core GEMM ===========================
// Single-pass fp16 (fp32 accumulate): ~2.4e-4 rel error, 3x fewer MMAs.
// Used for vproj / ffn1 / ffn2 (error-tolerant residual branches).
__global__ void __launch_bounds__(256, 2) gemm_f16(
    const float* __restrict__ A, const float* __restrict__ W,
    const float* __restrict__ bias, const float* __restrict__ resid,
    const unsigned char* __restrict__ mask,
    float* __restrict__ Cc, int M, int N, int K, int ldc, int coloff, int epi)
{
    __shared__ __align__(16) unsigned AsH[8*32*4];
    __shared__ __align__(16) unsigned BsH[4*32*2*2];

    int tid = threadIdx.x;
    int wid = tid >> 5, lane = tid & 31;
    int wm = wid & 3, wn = wid >> 2;
    int row0 = blockIdx.y * 128;
    int col0 = blockIdx.x * 64;

    int arow = tid >> 1;
    int ak0  = (tid & 1) * 8;
    int brow = tid >> 2;
    int bk0  = (tid & 3) * 4;

    int grow = row0 + arow;
    int gcol = col0 + brow;
    bool avalid = grow < M;
    bool bvalid = gcol < N;
    const float* Aptr = A + (size_t)grow * K + ak0;
    const float* Wptr = W + (size_t)gcol * K + bk0;

    int a_mt = arow >> 4;
    int a_g  = arow & 15;
    int a_laneg = a_g & 7;
    int a_regrow = a_g >> 3;
    int b_nt  = brow >> 3;
    int b_g   = brow & 7;
    int b_pair = b_nt >> 1;
    int b_sub  = b_nt & 1;

    float acc[2][4][4];
    #pragma unroll
    for (int i = 0; i < 2; i++)
        #pragma unroll
        for (int j = 0; j < 4; j++)
            #pragma unroll
            for (int r = 0; r < 4; r++) acc[i][j][r] = 0.f;

    float4 zf4 = make_float4(0.f, 0.f, 0.f, 0.f);
    float4 aR0 = avalid ? *(const float4*)(Aptr)     : zf4;
    float4 aR1 = avalid ? *(const float4*)(Aptr + 4) : zf4;
    float4 bR0 = bvalid ? *(const float4*)(Wptr)     : zf4;

    for (int kt = 0; kt < K; kt += 16) {
        {
            int reg = a_regrow + 2 * (ak0 >> 3);
            int t4  = (ak0 & 7) >> 1;
            int base = (a_mt * 32 + a_laneg * 4 + t4) * 4 + reg;
            AsH[base] = pack_h2(aR0.x, aR0.y);
            base = (a_mt * 32 + a_laneg * 4 + t4 + 1) * 4 + reg;
            AsH[base] = pack_h2(aR0.z, aR0.w);
            int ak1 = ak0 + 4;
            reg = a_regrow + 2 * (ak1 >> 3);
            t4  = (ak1 & 7) >> 1;
            base = (a_mt * 32 + a_laneg * 4 + t4) * 4 + reg;
            AsH[base] = pack_h2(aR1.x, aR1.y);
            base = (a_mt * 32 + a_laneg * 4 + t4 + 1) * 4 + reg;
            AsH[base] = pack_h2(aR1.z, aR1.w);
            int breg = bk0 >> 3;
            int bt4  = (bk0 & 7) >> 1;
            base = ((b_pair * 32 + b_g * 4 + bt4) * 2 + b_sub) * 2 + breg;
            BsH[base] = pack_h2(bR0.x, bR0.y);
            base = ((b_pair * 32 + b_g * 4 + bt4 + 1) * 2 + b_sub) * 2 + breg;
            BsH[base] = pack_h2(bR0.z, bR0.w);
        }
        __syncthreads();

        if (kt + 16 < K) {
            aR0 = avalid ? *(const float4*)(Aptr + kt + 16)     : zf4;
            aR1 = avalid ? *(const float4*)(Aptr + kt + 16 + 4) : zf4;
            bR0 = bvalid ? *(const float4*)(Wptr + kt + 16)     : zf4;
        }

        uint4 aH[2], bH[2];
        #pragma unroll
        for (int mt = 0; mt < 2; mt++) {
            int idx = ((wm * 2 + mt) * 32 + lane) * 4;
            aH[mt] = *(const uint4*)&AsH[idx];
        }
        #pragma unroll
        for (int np = 0; np < 2; np++) {
            int idx = ((wn * 2 + np) * 32 + lane) * 4;
            bH[np] = *(const uint4*)&BsH[idx];
        }
        #pragma unroll
        for (int mt = 0; mt < 2; mt++) {
            #pragma unroll
            for (int nt = 0; nt < 4; nt++) {
                int np = nt >> 1, sub = nt & 1;
                unsigned bh0 = sub ? bH[np].z : bH[np].x;
                unsigned bh1 = sub ? bH[np].w : bH[np].y;
                float* c = acc[mt][nt];
                mma_f16(c[0], c[1], c[2], c[3],
                        aH[mt].x, aH[mt].y, aH[mt].z, aH[mt].w, bh0, bh1);
            }
        }
        __syncthreads();
    }

    int g = lane >> 2, t4 = lane & 3;
    #pragma unroll
    for (int mt = 0; mt < 2; mt++) {
        #pragma unroll
        for (int nt = 0; nt < 4; nt++) {
            int r = row0 + wm * 32 + mt * 16 + g;
            int c = col0 + wn * 32 + nt * 8 + t4 * 2;
            if (c >= N) continue;
            float b0 = bias[c], b1 = bias[c + 1];
            #pragma unroll
            for (int half = 0; half < 2; half++) {
                int rr = r + half * 8;
                if (rr >= M) continue;
                float v0 = acc[mt][nt][half * 2 + 0] + b0;
                float v1 = acc[mt][nt][half * 2 + 1] + b1;
                if (epi == 1) { v0 = fmaxf(v0, 0.f); v1 = fmaxf(v1, 0.f); }
                else if (epi == 2) {
                    const float* rp = resid + (size_t)rr * ldc + coloff + c;
                    v0 += rp[0]; v1 += rp[1];
                }
                else if (epi == 3 && mask[rr]) { v0 = 0.f; v1 = 0.f; }
                float2 o; o.x = v0; o.y = v1;
                *(float2*)(Cc + (size_t)rr * ldc + coloff + c) = o;
            }
        }
    }
}

// ---------------- Self-attention (flash-style, q-range split 3-way) --------
__global__ void __launch_bounds__(256) attn_kernel(
    const float* __restrict__ qkv, float* __restrict__ sa)
{
    int b = blockIdx.x / H_;
    int h = blockIdx.x % H_;
    int q0 = blockIdx.y * 100;          // q chunk [q0, q0+100)
    extern __shared__ float sm[];
    float* Ks = sm;
    float* Vs = sm + NQ_ * DH_;
    int tid = threadIdx.x;

    for (int i = tid; i < NQ_ * DH_; i += 256) {
        int r = i >> 5, d = i & 31;
        const float* base = qkv + ((size_t)(b * NQ_ + r)) * 768 + h * 32 + d;
        Ks[i] = base[256];
        Vs[i] = base[512];
    }
    __syncthreads();

    for (int q = q0 + tid; q < q0 + 100; q += 256) {
        float4 qv[8];
        const float4* qb = (const float4*)(qkv + ((size_t)(b * NQ_ + q)) * 768 + h * 32);
        #pragma unroll
        for (int u = 0; u < 8; u++) qv[u] = qb[u];

        float m = -1e30f, s = 0.f;
        float acc[32];
        #pragma unroll
        for (int d = 0; d < 32; d++) acc[d] = 0.f;

        for (int k = 0; k < NQ_; k++) {
            const float4* kb = (const float4*)(Ks + k * 32);
            float dot = 0.f;
            #pragma unroll
            for (int u = 0; u < 8; u++) {
                float4 kv = kb[u];
                dot += qv[u].x * kv.x + qv[u].y * kv.y + qv[u].z * kv.z + qv[u].w * kv.w;
            }
            dot *= 0.17677669529663687f;   // 1/sqrt(32)
            float nm = fmaxf(m, dot);
            float corr = __expf(m - nm);
            float e = __expf(dot - nm);
            s = s * corr + e;
            const float4* vb = (const float4*)(Vs + k * 32);
            #pragma unroll
            for (int u = 0; u < 8; u++) {
                float4 vv = vb[u];
                acc[4*u+0] = acc[4*u+0] * corr + e * vv.x;
                acc[4*u+1] = acc[4*u+1] * corr + e * vv.y;
                acc[4*u+2] = acc[4*u+2] * corr + e * vv.z;
                acc[4*u+3] = acc[4*u+3] * corr + e * vv.w;
            }
            m = nm;
        }
        float inv = 1.f / s;
        float* outp = sa + ((size_t)(b * NQ_ + q)) * C_ + h * 32;
        #pragma unroll
        for (int d = 0; d < 32; d++) outp[d] = acc[d] * inv;
    }
}

// ---------------- Deformable sampling (warp per head, lane = channel) -------
__global__ void __launch_bounds__(256) deform_kernel(
    const float* __restrict__ v, const float* __restrict__ offb,
    const float* __restrict__ awb, const float* __restrict__ refp,
    float* __restrict__ ca)
{
    int bq = blockIdx.x;
    int h = threadIdx.x >> 5;
    int lane = threadIdx.x & 31;

    float lg = (lane < 12) ? awb[(size_t)bq * 96 + h * 12 + lane] : -INFINITY;
    float mx = lg;
    #pragma unroll
    for (int o = 16; o; o >>= 1) mx = fmaxf(mx, __shfl_xor_sync(0xffffffffu, mx, o));
    float e = (lane < 12) ? __expf(lg - mx) : 0.f;
    float ssum = e;
    #pragma unroll
    for (int o = 16; o; o >>= 1) ssum += __shfl_xor_sync(0xffffffffu, ssum, o);
    float myaw = e / ssum;

    const int Wl[3] = {128, 64, 32};
    const int Hl[3] = {128, 64, 32};
    const int st[3] = {0, 16384, 20480};

    float acc = 0.f;
    const float* offrow = offb + (size_t)bq * 192 + h * 24;
    const float* refrow = refp + (size_t)bq * 6;
    int bbase = (bq / NQ_) * LEN_IN_;

    #pragma unroll
    for (int l = 0; l < 3; l++) {
        float Wf = (float)Wl[l], Hf = (float)Hl[l];
        float rx = refrow[l * 2 + 0];
        float ry = refrow[l * 2 + 1];
        #pragma unroll
        for (int p = 0; p < 4; p++) {
            float ox = offrow[(l * 4 + p) * 2 + 0];
            float oy = offrow[(l * 4 + p) * 2 + 1];
            float lx = rx + ox / Wf;
            float ly = ry + oy / Hf;
            float x = lx * Wf - 0.5f;
            float y = ly * Hf - 0.5f;
            float x0 = floorf(x), y0 = floorf(y);
            float fx = x - x0, fy = y - y0;
            int ix = (int)x0, iy = (int)y0;
            float a = __shfl_sync(0xffffffffu, myaw, l * 4 + p);
            #pragma unroll
            for (int dy = 0; dy < 2; dy++) {
                int yi = iy + dy;
                if (yi < 0 || yi >= Hl[l]) continue;
                float wy = dy ? fy : (1.f - fy);
                #pragma unroll
                for (int dx = 0; dx < 2; dx++) {
                    int xi = ix + dx;
                    if (xi < 0 || xi >= Wl[l]) continue;
                    float w = wy * (dx ? fx : (1.f - fx));
                    int pos = st[l] + yi * Wl[l] + xi;
                    acc += a * w * v[((size_t)(bbase + pos) * H_ + h) * DH_ + lane];
                }
            }
        }
    }
    ca[(size_t)bq * C_ + h * DH_ + lane] = acc;
}

// ---------------------------------------------------------------------------
extern "C" void kernel_launch(void* const* d_in, const int* in_sizes, int n_in,
                              void* d_out, int out_size)
{
    const float* tgt        = (const float*)d_in[0];
    const float* memory     = (const float*)d_in[1];
    const float* query_pos  = (const float*)d_in[3];
    const float* qref       = (const float*)d_in[5];
    const unsigned char* kpm = (const unsigned char*)d_in[7];
    const float* ln1g = (const float*)d_in[9];
    const float* ln1b = (const float*)d_in[10];
    const float* ln2g = (const float*)d_in[11];
    const float* ln2b = (const float*)d_in[12];
    const float* ln3g = (const float*)d_in[13];
    const float* ln3b = (const float*)d_in[14];
    const float* attn_in_w  = (const float*)d_in[15];
    const float* attn_in_b  = (const float*)d_in[16];
    const float* attn_out_w = (const float*)d_in[17];
    const float* attn_out_b = (const float*)d_in[18];
    const float* off_w  = (const float*)d_in[19];
    const float* off_b  = (const float*)d_in[20];
    const float* aw_w   = (const float*)d_in[21];
    const float* aw_b   = (const float*)d_in[22];
    const float* vproj_w = (const float*)d_in[23];
    const float* vproj_b = (const float*)d_in[24];
    const float* oproj_w = (const float*)d_in[25];
    const float* oproj_b = (const float*)d_in[26];
    const float* ffn1_w = (const float*)d_in[27];
    const float* ffn1_b = (const float*)d_in[28];
    const float* ffn2_w = (const float*)d_in[29];
    const float* ffn2_b = (const float*)d_in[30];
    float* out = (float*)d_out;

    float *p_t2, *p_qk, *p_qkv, *p_sa, *p_tgt1, *p_tgt2, *p_v, *p_off, *p_aw, *p_ca, *p_hid;
    cudaGetSymbolAddress((void**)&p_t2,   g_t2);
    cudaGetSymbolAddress((void**)&p_qk,   g_qk);
    cudaGetSymbolAddress((void**)&p_qkv,  g_qkv);
    cudaGetSymbolAddress((void**)&p_sa,   g_sa);
    cudaGetSymbolAddress((void**)&p_tgt1, g_tgt1);
    cudaGetSymbolAddress((void**)&p_tgt2, g_tgt2);
    cudaGetSymbolAddress((void**)&p_v,    g_v);
    cudaGetSymbolAddress((void**)&p_off,  g_off);
    cudaGetSymbolAddress((void**)&p_aw,   g_aw);
    cudaGetSymbolAddress((void**)&p_ca,   g_ca);
    cudaGetSymbolAddress((void**)&p_hid,  g_hid);

    int attn_smem = NQ_ * DH_ * 2 * sizeof(float);   // 76800
    cudaFuncSetAttribute(attn_kernel, cudaFuncAttributeMaxDynamicSharedMemorySize, attn_smem);

    dim3 blk(256);
    const int MT_TILES = (MTGT + 127) / 128;   // 38
    const int MV_TILES = MV / 128;             // 2688

    // 1) LN1 -> t2, qk = t2 + query_pos
    ln_kernel<<<MTGT, blk>>>(tgt, ln1g, ln1b, query_pos, p_t2, p_qk);

    // 2) Q,K = qk @ Wqk^T ; V = t2 @ Wv^T  (into qkv[.,768])
    gemm_mma<<<dim3(8, MT_TILES), blk>>>(p_qk, attn_in_w, attn_in_b,
        nullptr, nullptr, p_qkv, MTGT, 512, C_, 768, 0, 0);
    gemm_mma<<<dim3(4, MT_TILES), blk>>>(p_t2, attn_in_w + 512*C_, attn_in_b + 512,
        nullptr, nullptr, p_qkv, MTGT, 256, C_, 768, 512, 0);

    // 3) self-attention -> sa   (q split 3-way for occupancy)
    attn_kernel<<<dim3(B_ * H_, 3), blk, attn_smem>>>(p_qkv, p_sa);

    // 4) tgt1 = tgt + sa @ attn_out_w^T + b
    gemm_mma<<<dim3(4, MT_TILES), blk>>>(p_sa, attn_out_w, attn_out_b,
        tgt, nullptr, p_tgt1, MTGT, C_, C_, C_, 0, 2);

    // 5) LN2 -> t2
    ln_kernel<<<MTGT, blk>>>(p_tgt1, ln2g, ln2b, nullptr, p_t2, nullptr);

    // 6) v = memory @ vproj^T + b, masked  (dominant GEMM, fp16x1)
    gemm_f16<<<dim3(4, MV_TILES), blk>>>(memory, vproj_w, vproj_b,
        nullptr, kpm, p_v, MV, C_, C_, C_, 0, 3);

    // 7) offsets and attention-weight logits
    gemm_mma<<<dim3(3, MT_TILES), blk>>>(p_t2, off_w, off_b,
        nullptr, nullptr, p_off, MTGT, 192, C_, 192, 0, 0);
    gemm_mma<<<dim3(2, MT_TILES), blk>>>(p_t2, aw_w, aw_b,
        nullptr, nullptr, p_aw, MTGT, 96, C_, 96, 0, 0);

    // 8) deformable sampling (softmax fused) -> ca
    deform_kernel<<<MTGT, blk>>>(p_v, p_off, p_aw, qref, p_ca);

    // 9) tgt2 = tgt1 + ca @ oproj^T + b
    gemm_mma<<<dim3(4, MT_TILES), blk>>>(p_ca, oproj_w, oproj_b,
        p_tgt1, nullptr, p_tgt2, MTGT, C_, C_, C_, 0, 2);

    // 10) LN3 -> t2
    ln_kernel<<<MTGT, blk>>>(p_tgt2, ln3g, ln3b, nullptr, p_t2, nullptr);

    // 11) FFN (fp16x1)
    gemm_f16<<<dim3(DFF_/64, MT_TILES), blk>>>(p_t2, ffn1_w, ffn1_b,
        nullptr, nullptr, p_hid, MTGT, DFF_, C_, DFF_, 0, 1);
    gemm_f16<<<dim3(4, MT_TILES), blk>>>(p_hid, ffn2_w, ffn2_b,
        p_tgt2, nullptr, out, MTGT, C_, DFF_, C_, 0, 2);
}